// round 1
// baseline (speedup 1.0000x reference)
#include <cuda_runtime.h>
#include <cuda_bf16.h>
#include <math.h>

#define Nn 10000
#define Ee 320000
#define ET (Ee + Nn)   // edges + self loops
#define DH 256
#define DOUT 64

// ---------------- device scratch (no cudaMalloc allowed) ----------------
__device__ float g_xl[Nn * DH];
__device__ float g_xr[Nn * DH];
__device__ float g_h[Nn * DH];
__device__ float g_logits[Nn * DOUT];
__device__ float g_scores[ET];
__device__ int   g_csr_src[ET];
__device__ int   g_cnt[Nn];
__device__ int   g_row_ptr[Nn + 1];
__device__ int   g_row_off[Nn];
__device__ int   g_flag_i64[1];

// ---------------- dtype detection for edge_index ----------------
__global__ void k_detect(const int* ei32) {
    if (threadIdx.x == 0 && blockIdx.x == 0) {
        int all0 = 1;
        for (int i = 0; i < 64; ++i) {
            if (ei32[2 * i + 1] != 0) { all0 = 0; break; }
        }
        g_flag_i64[0] = all0;
    }
}

__device__ __forceinline__ int edge_val(const void* ei, long long idx, int is64) {
    if (is64) return (int)((const long long*)ei)[idx];
    return ((const int*)ei)[idx];
}

// ---------------- CSR build ----------------
__global__ void k_zero_cnt() {
    int i = blockIdx.x * blockDim.x + threadIdx.x;
    if (i < Nn) g_cnt[i] = 0;
}

__global__ void k_hist(const void* ei) {
    int e = blockIdx.x * blockDim.x + threadIdx.x;
    if (e >= ET) return;
    int is64 = g_flag_i64[0];
    int dst = (e >= Ee) ? (e - Ee) : edge_val(ei, (long long)Ee + e, is64);
    atomicAdd(&g_cnt[dst], 1);
}

__global__ void k_scan() {
    __shared__ int s[1024];
    int tid = threadIdx.x;
    const int CH = (Nn + 1023) / 1024;  // 10
    int base = tid * CH;
    int local = 0;
    for (int i = 0; i < CH; ++i) {
        int idx = base + i;
        if (idx < Nn) local += g_cnt[idx];
    }
    s[tid] = local;
    __syncthreads();
    // Hillis-Steele inclusive scan
    for (int off = 1; off < 1024; off <<= 1) {
        int v = s[tid];
        int add = (tid >= off) ? s[tid - off] : 0;
        __syncthreads();
        s[tid] = v + add;
        __syncthreads();
    }
    int run = (tid > 0) ? s[tid - 1] : 0;  // exclusive prefix
    for (int i = 0; i < CH; ++i) {
        int idx = base + i;
        if (idx < Nn) {
            g_row_ptr[idx] = run;
            g_row_off[idx] = run;
            run += g_cnt[idx];
        }
    }
    if (tid == 1023) g_row_ptr[Nn] = run;
}

__global__ void k_scatter(const void* ei) {
    int e = blockIdx.x * blockDim.x + threadIdx.x;
    if (e >= ET) return;
    int is64 = g_flag_i64[0];
    int src, dst;
    if (e >= Ee) {
        src = dst = e - Ee;
    } else {
        src = edge_val(ei, (long long)e, is64);
        dst = edge_val(ei, (long long)Ee + e, is64);
    }
    int pos = atomicAdd(&g_row_off[dst], 1);
    g_csr_src[pos] = src;
}

// ---------------- SGEMM: C[M,Nc] = A[M,K] @ B[K,Nc] + bias ----------------
// 64x64 tile, 256 threads, 4x4 micro-tile per thread, TK=16.
#define TM 64
#define TN 64
#define TK 16
__global__ __launch_bounds__(256) void k_sgemm_bias(
    const float* __restrict__ A, const float* __restrict__ B,
    const float* __restrict__ bias, float* __restrict__ C,
    int M, int Nc, int K)
{
    __shared__ float As[TK][TM];
    __shared__ float Bs[TK][TN];
    int tid = threadIdx.x;
    int tx = tid & 15, ty = tid >> 4;
    int row0 = blockIdx.y * TM;
    int col0 = blockIdx.x * TN;

    float c[4][4] = {};

    int am  = tid >> 2;          // 0..63 : A tile row
    int akq = (tid & 3) * 4;     // 0,4,8,12 : A tile k offset
    int bk  = tid >> 4;          // 0..15 : B tile k row
    int bn  = (tid & 15) * 4;    // 0..60 : B tile col

    for (int k0 = 0; k0 < K; k0 += TK) {
        float4 av = make_float4(0.f, 0.f, 0.f, 0.f);
        int ar = row0 + am;
        if (ar < M) av = *(const float4*)(A + (size_t)ar * K + k0 + akq);
        As[akq + 0][am] = av.x;
        As[akq + 1][am] = av.y;
        As[akq + 2][am] = av.z;
        As[akq + 3][am] = av.w;

        float4 bv = *(const float4*)(B + (size_t)(k0 + bk) * Nc + col0 + bn);
        *(float4*)&Bs[bk][bn] = bv;
        __syncthreads();

#pragma unroll
        for (int kk = 0; kk < TK; ++kk) {
            float4 a4 = *(float4*)&As[kk][ty * 4];
            float4 b4 = *(float4*)&Bs[kk][tx * 4];
            float ar_[4] = {a4.x, a4.y, a4.z, a4.w};
            float br_[4] = {b4.x, b4.y, b4.z, b4.w};
#pragma unroll
            for (int i = 0; i < 4; ++i)
#pragma unroll
                for (int j = 0; j < 4; ++j)
                    c[i][j] = fmaf(ar_[i], br_[j], c[i][j]);
        }
        __syncthreads();
    }

#pragma unroll
    for (int i = 0; i < 4; ++i) {
        int r = row0 + ty * 4 + i;
        if (r < M) {
            int cc = col0 + tx * 4;
            float4 o;
            o.x = c[i][0] + bias[cc + 0];
            o.y = c[i][1] + bias[cc + 1];
            o.z = c[i][2] + bias[cc + 2];
            o.w = c[i][3] + bias[cc + 3];
            *(float4*)(C + (size_t)r * Nc + cc) = o;
        }
    }
}

// ---------------- GATv2 layer (per-node block) ----------------
__device__ __forceinline__ float warp_sum(float v) {
#pragma unroll
    for (int o = 16; o > 0; o >>= 1) v += __shfl_xor_sync(0xffffffffu, v, o);
    return v;
}

__global__ __launch_bounds__(256) void k_gat_layer(
    const float* __restrict__ xl, const float* __restrict__ xr,
    const float* __restrict__ att, const float* __restrict__ bias,
    float* __restrict__ out, int applyRelu)
{
    int node = blockIdx.x;
    int tid = threadIdx.x;
    int lane = tid & 31, w = tid >> 5;

    __shared__ float s_xr[DH];
    __shared__ float s_att[DH];
    __shared__ float s_red[8];
    __shared__ float s_m, s_inv;

    s_xr[tid]  = xr[(size_t)node * DH + tid];
    s_att[tid] = att[tid];
    __syncthreads();

    int beg = g_row_ptr[node];
    int end = g_row_ptr[node + 1];

    // Phase A: warp-per-edge scores
    float wmax = -INFINITY;
    for (int e = beg + w; e < end; e += 8) {
        int src = g_csr_src[e];
        const float* xs = xl + (size_t)src * DH;
        float p = 0.f;
#pragma unroll
        for (int j = 0; j < 8; ++j) {
            int d = lane + j * 32;
            float v = xs[d] + s_xr[d];
            v = (v > 0.f) ? v : 0.2f * v;
            p = fmaf(s_att[d], v, p);
        }
        p = warp_sum(p);
        if (lane == 0) g_scores[e] = p;
        wmax = fmaxf(wmax, p);
    }
    if (lane == 0) s_red[w] = wmax;
    __syncthreads();
    if (tid == 0) {
        float m = s_red[0];
#pragma unroll
        for (int i = 1; i < 8; ++i) m = fmaxf(m, s_red[i]);
        s_m = m;
    }
    __syncthreads();
    float m = s_m;

    // Phase A2: exp + sum
    float ps = 0.f;
    for (int e = beg + tid; e < end; e += 256) {
        float es = expf(g_scores[e] - m);
        g_scores[e] = es;
        ps += es;
    }
    ps = warp_sum(ps);
    __syncthreads();              // protect s_red reuse
    if (lane == 0) s_red[w] = ps;
    __syncthreads();
    if (tid == 0) {
        float s = 0.f;
#pragma unroll
        for (int i = 0; i < 8; ++i) s += s_red[i];
        s_inv = 1.f / s;
    }
    __syncthreads();
    float inv = s_inv;

    // Phase B: thread-per-dim weighted aggregation
    float acc = 0.f;
    int e = beg;
#pragma unroll 1
    for (; e + 4 <= end; e += 4) {
        int s0 = g_csr_src[e + 0], s1 = g_csr_src[e + 1];
        int s2 = g_csr_src[e + 2], s3 = g_csr_src[e + 3];
        float a0 = g_scores[e + 0], a1 = g_scores[e + 1];
        float a2 = g_scores[e + 2], a3 = g_scores[e + 3];
        float v0 = xl[(size_t)s0 * DH + tid];
        float v1 = xl[(size_t)s1 * DH + tid];
        float v2 = xl[(size_t)s2 * DH + tid];
        float v3 = xl[(size_t)s3 * DH + tid];
        acc = fmaf(a0, v0, acc);
        acc = fmaf(a1, v1, acc);
        acc = fmaf(a2, v2, acc);
        acc = fmaf(a3, v3, acc);
    }
    for (; e < end; ++e) {
        acc = fmaf(g_scores[e], xl[(size_t)g_csr_src[e] * DH + tid], acc);
    }

    float r = acc * inv + bias[tid];
    if (applyRelu) r = fmaxf(r, 0.f);
    out[(size_t)node * DH + tid] = r;
}

// ---------------- log_softmax over 64-dim rows ----------------
__global__ __launch_bounds__(256) void k_logsoftmax(const float* __restrict__ in,
                                                    float* __restrict__ out) {
    int row = blockIdx.x * 8 + (threadIdx.x >> 5);
    if (row >= Nn) return;
    int lane = threadIdx.x & 31;
    float v0 = in[(size_t)row * DOUT + lane];
    float v1 = in[(size_t)row * DOUT + 32 + lane];
    float m = fmaxf(v0, v1);
#pragma unroll
    for (int o = 16; o > 0; o >>= 1) m = fmaxf(m, __shfl_xor_sync(0xffffffffu, m, o));
    float s = expf(v0 - m) + expf(v1 - m);
    s = warp_sum(s);
    float lse = m + logf(s);
    out[(size_t)row * DOUT + lane]       = v0 - lse;
    out[(size_t)row * DOUT + 32 + lane]  = v1 - lse;
}

// ---------------- launch ----------------
extern "C" void kernel_launch(void* const* d_in, const int* in_sizes, int n_in,
                              void* d_out, int out_size) {
    const float* x    = (const float*)d_in[0];
    const float* W1l  = (const float*)d_in[1];
    const float* b1l  = (const float*)d_in[2];
    const float* W1r  = (const float*)d_in[3];
    const float* b1r  = (const float*)d_in[4];
    const float* att1 = (const float*)d_in[5];
    const float* bias1= (const float*)d_in[6];
    const float* W2l  = (const float*)d_in[7];
    const float* b2l  = (const float*)d_in[8];
    const float* W2r  = (const float*)d_in[9];
    const float* b2r  = (const float*)d_in[10];
    const float* att2 = (const float*)d_in[11];
    const float* bias2= (const float*)d_in[12];
    const float* Wout = (const float*)d_in[13];
    const float* bout = (const float*)d_in[14];
    const void*  ei   = d_in[15];
    float* out = (float*)d_out;

    float *xl, *xr, *h, *logits;
    cudaGetSymbolAddress((void**)&xl, g_xl);
    cudaGetSymbolAddress((void**)&xr, g_xr);
    cudaGetSymbolAddress((void**)&h,  g_h);
    cudaGetSymbolAddress((void**)&logits, g_logits);

    // edge dtype detect + CSR build
    k_detect<<<1, 32>>>((const int*)ei);
    k_zero_cnt<<<(Nn + 255) / 256, 256>>>();
    k_hist<<<(ET + 255) / 256, 256>>>(ei);
    k_scan<<<1, 1024>>>();
    k_scatter<<<(ET + 255) / 256, 256>>>(ei);

    dim3 g256(DH / TN, (Nn + TM - 1) / TM);
    dim3 g64(DOUT / TN, (Nn + TM - 1) / TM);

    // layer 1
    k_sgemm_bias<<<g256, 256>>>(x, W1l, b1l, xl, Nn, DH, DH);
    k_sgemm_bias<<<g256, 256>>>(x, W1r, b1r, xr, Nn, DH, DH);
    k_gat_layer<<<Nn, 256>>>(xl, xr, att1, bias1, h, 1);

    // layer 2
    k_sgemm_bias<<<g256, 256>>>(h, W2l, b2l, xl, Nn, DH, DH);
    k_sgemm_bias<<<g256, 256>>>(h, W2r, b2r, xr, Nn, DH, DH);
    k_gat_layer<<<Nn, 256>>>(xl, xr, att2, bias2, h, 1);

    // output head
    k_sgemm_bias<<<g64, 256>>>(h, Wout, bout, logits, Nn, DOUT, DH);
    k_logsoftmax<<<(Nn + 7) / 8, 256>>>(logits, out);
}

// round 2
// speedup vs baseline: 1.4395x; 1.4395x over previous
#include <cuda_runtime.h>
#include <cuda_bf16.h>
#include <math.h>

#define Nn 10000
#define Ee 320000
#define ET (Ee + Nn)   // edges + self loops
#define DH 256
#define DOUT 64

// ---------------- device scratch (no cudaMalloc allowed) ----------------
__device__ float g_xl[Nn * DH];
__device__ float g_xr[Nn * DH];
__device__ float g_h[Nn * DH];
__device__ float g_logits[Nn * DOUT];
__device__ float g_scores[ET];
__device__ int   g_csr_src[ET];
__device__ int   g_cnt[Nn];
__device__ int   g_row_ptr[Nn + 1];
__device__ int   g_row_off[Nn];
__device__ int   g_flag_i64[1];

// ---------------- dtype detection for edge_index ----------------
__global__ void k_detect(const int* ei32) {
    if (threadIdx.x == 0 && blockIdx.x == 0) {
        int all0 = 1;
        for (int i = 0; i < 64; ++i) {
            if (ei32[2 * i + 1] != 0) { all0 = 0; break; }
        }
        g_flag_i64[0] = all0;
    }
}

__device__ __forceinline__ int edge_val(const void* ei, long long idx, int is64) {
    if (is64) return (int)((const long long*)ei)[idx];
    return ((const int*)ei)[idx];
}

// ---------------- CSR build ----------------
__global__ void k_zero_cnt() {
    int i = blockIdx.x * blockDim.x + threadIdx.x;
    if (i < Nn) g_cnt[i] = 0;
}

__global__ void k_hist(const void* ei) {
    int e = blockIdx.x * blockDim.x + threadIdx.x;
    if (e >= ET) return;
    int is64 = g_flag_i64[0];
    int dst = (e >= Ee) ? (e - Ee) : edge_val(ei, (long long)Ee + e, is64);
    atomicAdd(&g_cnt[dst], 1);
}

// hierarchical shuffle scan: 1024 threads x 10 elems
__global__ __launch_bounds__(1024) void k_scan() {
    __shared__ int wsum[32];
    int tid = threadIdx.x;
    int lane = tid & 31, w = tid >> 5;
    int base = tid * 10;
    int c[10];
    int s = 0;
#pragma unroll
    for (int i = 0; i < 10; ++i) {
        int idx = base + i;
        c[i] = (idx < Nn) ? g_cnt[idx] : 0;
        s += c[i];
    }
    int incl = s;
#pragma unroll
    for (int o = 1; o < 32; o <<= 1) {
        int v = __shfl_up_sync(0xffffffffu, incl, o);
        if (lane >= o) incl += v;
    }
    if (lane == 31) wsum[w] = incl;
    __syncthreads();
    if (w == 0) {
        int v = wsum[lane];
        int wi = v;
#pragma unroll
        for (int o = 1; o < 32; o <<= 1) {
            int t = __shfl_up_sync(0xffffffffu, wi, o);
            if (lane >= o) wi += t;
        }
        wsum[lane] = wi;
    }
    __syncthreads();
    int excl = incl - s + (w > 0 ? wsum[w - 1] : 0);
    int run = excl;
#pragma unroll
    for (int i = 0; i < 10; ++i) {
        int idx = base + i;
        if (idx < Nn) {
            g_row_ptr[idx] = run;
            g_row_off[idx] = run;
            run += c[i];
        }
    }
    if (tid == 0) g_row_ptr[Nn] = ET;
}

__global__ void k_scatter(const void* ei) {
    int e = blockIdx.x * blockDim.x + threadIdx.x;
    if (e >= ET) return;
    int is64 = g_flag_i64[0];
    int src, dst;
    if (e >= Ee) {
        src = dst = e - Ee;
    } else {
        src = edge_val(ei, (long long)e, is64);
        dst = edge_val(ei, (long long)Ee + e, is64);
    }
    int pos = atomicAdd(&g_row_off[dst], 1);
    g_csr_src[pos] = src;
}

// ---------------- TF32 tensor-core GEMM ----------------
// C[M,Nc] = A[M,K] @ B[K,Nc] + bias, via mma.sync.m16n8k8.tf32
// Block tile BM=128 x BN, BK=32, 256 threads (8 warps).
// Warp tile: (MT*16) x 32, NT=4 n-subtiles of 8.

__device__ __forceinline__ unsigned f2tf32(float v) {
    unsigned o;
    asm volatile("cvt.rna.tf32.f32 %0, %1;" : "=r"(o) : "f"(v));
    return o;
}

template<int BN, int WARPS_M, int MT>
__global__ __launch_bounds__(256) void k_gemm_tf32(
    const float* __restrict__ A, const float* __restrict__ B,
    const float* __restrict__ bias, float* __restrict__ C,
    int M, int Nc, int K)
{
    constexpr int BM = 128;
    constexpr int BK = 32;
    constexpr int NT = 4;
    constexpr int ASTR = 36;       // padded lead (floats), 144B rows (16B aligned)
    constexpr int BSTR = BN + 8;   // stride%32==8 -> conflict-free frag loads

    __shared__ unsigned As[BM][ASTR];
    __shared__ unsigned Bs[BK][BSTR];

    int tid = threadIdx.x;
    int lane = tid & 31;
    int wid = tid >> 5;
    int gid = lane >> 2;     // 0..7
    int tin = lane & 3;      // 0..3

    int wm = wid % WARPS_M;
    int wn = wid / WARPS_M;
    int mbase = wm * (MT * 16);
    int nbase = wn * 32;

    int row0 = blockIdx.y * BM;
    int col0 = blockIdx.x * BN;

    float c[MT][NT][4];
#pragma unroll
    for (int i = 0; i < MT; ++i)
#pragma unroll
        for (int j = 0; j < NT; ++j)
#pragma unroll
            for (int q = 0; q < 4; ++q) c[i][j][q] = 0.f;

    constexpr int AF4 = (BM * BK) / 4 / 256;   // float4 loads per thread for A = 4
    constexpr int BF4 = (BK * BN) / 4 / 256;   // for B
    constexpr int BROWF4 = BN / 4;

    for (int k0 = 0; k0 < K; k0 += BK) {
        // load A tile
#pragma unroll
        for (int i = 0; i < AF4; ++i) {
            int idx = tid + i * 256;
            int r = idx >> 3;
            int c4 = (idx & 7) * 4;
            float4 v = make_float4(0.f, 0.f, 0.f, 0.f);
            if (row0 + r < M)
                v = *(const float4*)(A + (size_t)(row0 + r) * K + k0 + c4);
            uint4 t;
            t.x = f2tf32(v.x); t.y = f2tf32(v.y);
            t.z = f2tf32(v.z); t.w = f2tf32(v.w);
            *(uint4*)&As[r][c4] = t;
        }
        // load B tile
#pragma unroll
        for (int i = 0; i < BF4; ++i) {
            int idx = tid + i * 256;
            int r = idx / BROWF4;
            int c4 = (idx % BROWF4) * 4;
            float4 v = *(const float4*)(B + (size_t)(k0 + r) * Nc + col0 + c4);
            uint4 t;
            t.x = f2tf32(v.x); t.y = f2tf32(v.y);
            t.z = f2tf32(v.z); t.w = f2tf32(v.w);
            *(uint4*)&Bs[r][c4] = t;
        }
        __syncthreads();

#pragma unroll
        for (int kk = 0; kk < BK; kk += 8) {
            unsigned a[MT][4];
#pragma unroll
            for (int mt = 0; mt < MT; ++mt) {
                int r = mbase + mt * 16 + gid;
                a[mt][0] = As[r][kk + tin];
                a[mt][1] = As[r + 8][kk + tin];
                a[mt][2] = As[r][kk + tin + 4];
                a[mt][3] = As[r + 8][kk + tin + 4];
            }
            unsigned b[NT][2];
#pragma unroll
            for (int nt = 0; nt < NT; ++nt) {
                int n = nbase + nt * 8 + gid;
                b[nt][0] = Bs[kk + tin][n];
                b[nt][1] = Bs[kk + tin + 4][n];
            }
#pragma unroll
            for (int mt = 0; mt < MT; ++mt)
#pragma unroll
                for (int nt = 0; nt < NT; ++nt) {
                    asm volatile(
                        "mma.sync.aligned.m16n8k8.row.col.f32.tf32.tf32.f32 "
                        "{%0,%1,%2,%3}, {%4,%5,%6,%7}, {%8,%9}, {%0,%1,%2,%3};\n"
                        : "+f"(c[mt][nt][0]), "+f"(c[mt][nt][1]),
                          "+f"(c[mt][nt][2]), "+f"(c[mt][nt][3])
                        : "r"(a[mt][0]), "r"(a[mt][1]), "r"(a[mt][2]), "r"(a[mt][3]),
                          "r"(b[nt][0]), "r"(b[nt][1]));
                }
        }
        __syncthreads();
    }

    // epilogue: + bias
#pragma unroll
    for (int mt = 0; mt < MT; ++mt) {
        int r0 = row0 + mbase + mt * 16 + gid;
        int r1 = r0 + 8;
#pragma unroll
        for (int nt = 0; nt < NT; ++nt) {
            int col = col0 + nbase + nt * 8 + tin * 2;
            float b0 = bias[col], b1 = bias[col + 1];
            if (r0 < M) {
                float2 o = make_float2(c[mt][nt][0] + b0, c[mt][nt][1] + b1);
                *(float2*)(C + (size_t)r0 * Nc + col) = o;
            }
            if (r1 < M) {
                float2 o = make_float2(c[mt][nt][2] + b0, c[mt][nt][3] + b1);
                *(float2*)(C + (size_t)r1 * Nc + col) = o;
            }
        }
    }
}

// ---------------- GATv2 layer (per-node block) ----------------
__device__ __forceinline__ float warp_sum(float v) {
#pragma unroll
    for (int o = 16; o > 0; o >>= 1) v += __shfl_xor_sync(0xffffffffu, v, o);
    return v;
}

__global__ __launch_bounds__(256) void k_gat_layer(
    const float* __restrict__ xl, const float* __restrict__ xr,
    const float* __restrict__ att, const float* __restrict__ bias,
    float* __restrict__ out, int applyRelu)
{
    int node = blockIdx.x;
    int tid = threadIdx.x;
    int lane = tid & 31, w = tid >> 5;

    __shared__ float s_xr[DH];
    __shared__ float s_att[DH];
    __shared__ float s_red[8];
    __shared__ float s_m, s_inv;

    s_xr[tid]  = xr[(size_t)node * DH + tid];
    s_att[tid] = att[tid];
    __syncthreads();

    int beg = g_row_ptr[node];
    int end = g_row_ptr[node + 1];

    // Phase A: warp-per-edge scores
    float wmax = -INFINITY;
    for (int e = beg + w; e < end; e += 8) {
        int src = g_csr_src[e];
        const float* xs = xl + (size_t)src * DH;
        float p = 0.f;
#pragma unroll
        for (int j = 0; j < 8; ++j) {
            int d = lane + j * 32;
            float v = xs[d] + s_xr[d];
            v = (v > 0.f) ? v : 0.2f * v;
            p = fmaf(s_att[d], v, p);
        }
        p = warp_sum(p);
        if (lane == 0) g_scores[e] = p;
        wmax = fmaxf(wmax, p);
    }
    if (lane == 0) s_red[w] = wmax;
    __syncthreads();
    if (tid == 0) {
        float m = s_red[0];
#pragma unroll
        for (int i = 1; i < 8; ++i) m = fmaxf(m, s_red[i]);
        s_m = m;
    }
    __syncthreads();
    float m = s_m;

    // Phase A2: exp + sum
    float ps = 0.f;
    for (int e = beg + tid; e < end; e += 256) {
        float es = expf(g_scores[e] - m);
        g_scores[e] = es;
        ps += es;
    }
    ps = warp_sum(ps);
    __syncthreads();
    if (lane == 0) s_red[w] = ps;
    __syncthreads();
    if (tid == 0) {
        float s = 0.f;
#pragma unroll
        for (int i = 0; i < 8; ++i) s += s_red[i];
        s_inv = 1.f / s;
    }
    __syncthreads();
    float inv = s_inv;

    // Phase B: thread-per-dim weighted aggregation
    float acc = 0.f;
    int e = beg;
#pragma unroll 1
    for (; e + 4 <= end; e += 4) {
        int s0 = g_csr_src[e + 0], s1 = g_csr_src[e + 1];
        int s2 = g_csr_src[e + 2], s3 = g_csr_src[e + 3];
        float a0 = g_scores[e + 0], a1 = g_scores[e + 1];
        float a2 = g_scores[e + 2], a3 = g_scores[e + 3];
        float v0 = xl[(size_t)s0 * DH + tid];
        float v1 = xl[(size_t)s1 * DH + tid];
        float v2 = xl[(size_t)s2 * DH + tid];
        float v3 = xl[(size_t)s3 * DH + tid];
        acc = fmaf(a0, v0, acc);
        acc = fmaf(a1, v1, acc);
        acc = fmaf(a2, v2, acc);
        acc = fmaf(a3, v3, acc);
    }
    for (; e < end; ++e) {
        acc = fmaf(g_scores[e], xl[(size_t)g_csr_src[e] * DH + tid], acc);
    }

    float r = acc * inv + bias[tid];
    if (applyRelu) r = fmaxf(r, 0.f);
    out[(size_t)node * DH + tid] = r;
}

// ---------------- log_softmax over 64-dim rows ----------------
__global__ __launch_bounds__(256) void k_logsoftmax(const float* __restrict__ in,
                                                    float* __restrict__ out) {
    int row = blockIdx.x * 8 + (threadIdx.x >> 5);
    if (row >= Nn) return;
    int lane = threadIdx.x & 31;
    float v0 = in[(size_t)row * DOUT + lane];
    float v1 = in[(size_t)row * DOUT + 32 + lane];
    float m = fmaxf(v0, v1);
#pragma unroll
    for (int o = 16; o > 0; o >>= 1) m = fmaxf(m, __shfl_xor_sync(0xffffffffu, m, o));
    float s = expf(v0 - m) + expf(v1 - m);
    s = warp_sum(s);
    float lse = m + logf(s);
    out[(size_t)row * DOUT + lane]       = v0 - lse;
    out[(size_t)row * DOUT + 32 + lane]  = v1 - lse;
}

// ---------------- launch ----------------
extern "C" void kernel_launch(void* const* d_in, const int* in_sizes, int n_in,
                              void* d_out, int out_size) {
    const float* x    = (const float*)d_in[0];
    const float* W1l  = (const float*)d_in[1];
    const float* b1l  = (const float*)d_in[2];
    const float* W1r  = (const float*)d_in[3];
    const float* b1r  = (const float*)d_in[4];
    const float* att1 = (const float*)d_in[5];
    const float* bias1= (const float*)d_in[6];
    const float* W2l  = (const float*)d_in[7];
    const float* b2l  = (const float*)d_in[8];
    const float* W2r  = (const float*)d_in[9];
    const float* b2r  = (const float*)d_in[10];
    const float* att2 = (const float*)d_in[11];
    const float* bias2= (const float*)d_in[12];
    const float* Wout = (const float*)d_in[13];
    const float* bout = (const float*)d_in[14];
    const void*  ei   = d_in[15];
    float* out = (float*)d_out;

    float *xl, *xr, *h, *logits;
    cudaGetSymbolAddress((void**)&xl, g_xl);
    cudaGetSymbolAddress((void**)&xr, g_xr);
    cudaGetSymbolAddress((void**)&h,  g_h);
    cudaGetSymbolAddress((void**)&logits, g_logits);

    // edge dtype detect + CSR build
    k_detect<<<1, 32>>>((const int*)ei);
    k_zero_cnt<<<(Nn + 255) / 256, 256>>>();
    k_hist<<<(ET + 255) / 256, 256>>>(ei);
    k_scan<<<1, 1024>>>();
    k_scatter<<<(ET + 255) / 256, 256>>>(ei);

    dim3 gBig(DH / 128, (Nn + 127) / 128);   // 2 x 79
    dim3 gOut(DOUT / 64, (Nn + 127) / 128);  // 1 x 79

    // layer 1
    k_gemm_tf32<128, 2, 4><<<gBig, 256>>>(x, W1l, b1l, xl, Nn, DH, DH);
    k_gemm_tf32<128, 2, 4><<<gBig, 256>>>(x, W1r, b1r, xr, Nn, DH, DH);
    k_gat_layer<<<Nn, 256>>>(xl, xr, att1, bias1, h, 1);

    // layer 2
    k_gemm_tf32<128, 2, 4><<<gBig, 256>>>(h, W2l, b2l, xl, Nn, DH, DH);
    k_gemm_tf32<128, 2, 4><<<gBig, 256>>>(h, W2r, b2r, xr, Nn, DH, DH);
    k_gat_layer<<<Nn, 256>>>(xl, xr, att2, bias2, h, 1);

    // output head
    k_gemm_tf32<64, 4, 2><<<gOut, 256>>>(h, Wout, bout, logits, Nn, DOUT, DH);
    k_logsoftmax<<<(Nn + 7) / 8, 256>>>(logits, out);
}